// round 7
// baseline (speedup 1.0000x reference)
#include <cuda_runtime.h>

typedef unsigned long long ULL;

// ---------------- device scratch (no allocations allowed) ----------------
// Stage-1 partial sums: [b][s][idx]  (b:256, s:32, idx:320 = (c*10+w)*2+comp)
__device__ float fpart_g[256 * 32 * 320];
// Pre-batchnorm output: [b][c*2+o]
__device__ float out_g[256 * 32];
// completion counter for last-block BN (zero-init; last block re-zeros it)
__device__ int done_ctr;

// ---------------- packed f32x2 FMA (FFMA2) ----------------
__device__ __forceinline__ ULL fma2(ULL a, ULL b, ULL c) {
    ULL d;
    asm("fma.rn.f32x2 %0, %1, %2, %3;" : "=l"(d) : "l"(a), "l"(b), "l"(c));
    return d;
}
__device__ __forceinline__ float2 u2f2(ULL v) {
    return make_float2(__uint_as_float((unsigned)(v & 0xffffffffULL)),
                       __uint_as_float((unsigned)(v >> 32)));
}

// ---------------- kernel 1: depthwise sliding filters (stage 1) ----------------
// grid (16 batch-groups, 32 segments), 256 threads = 16 channels x 16 batches.
// Each thread: ONE (batch, channel), walks 128 positions, fully unrolled.
// f[b,w,c] = sum_p x[b,p,c] * Wpad[p - w + 9],  Wpad[lp] = W[lp-9] (zero-padded)
__global__ void __launch_bounds__(256) stage1_kernel(const float* __restrict__ x,
                                                     const float* __restrict__ wr,
                                                     const float* __restrict__ wi) {
    __shared__ __align__(16) ULL ws[137 * 16];   // [i][c]: Wpad[ps+i] for channel c

    int bg  = blockIdx.x;          // 0..15
    int s   = blockIdx.y;          // 0..31
    int tid = threadIdx.x;
    int c   = tid & 15;
    int bl  = tid >> 4;
    int ps  = s * 128;

    // cooperative weight gather with zero-pad: ws[i*16+cc] = {wr[cc][l], wi[cc][l]}
    {
        int cc = tid >> 4;
        for (int i = tid & 15; i < 137; i += 16) {
            int l = ps + i - 9;
            float a = 0.f, b = 0.f;
            if (l >= 0 && l < 4087) {
                a = wr[cc * 4087 + l];
                b = wi[cc * 4087 + l];
            }
            float2 v = make_float2(a, b);
            ws[i * 16 + cc] = *(ULL*)&v;
        }
    }
    __syncthreads();

    int b = bg * 16 + bl;
    const ULL* xp = (const ULL*)x + ((size_t)b * 4096 + ps) * 16 + c;

    // rotating window: slot m holds Wpad[ps + lp] with lp % 10 == m
    ULL wbuf[10];
#pragma unroll
    for (int k = 0; k < 9; k++) wbuf[k] = ws[k * 16 + c];

    ULL acc[10];
#pragma unroll
    for (int w = 0; w < 10; w++) acc[w] = 0ULL;

#pragma unroll
    for (int t = 0; t < 128; t++) {
        ULL xv = xp[(size_t)t * 16];
        wbuf[(t + 9) % 10] = ws[(t + 9) * 16 + c];    // lp = t+9
#pragma unroll
        for (int w = 0; w < 10; w++)
            acc[w] = fma2(xv, wbuf[(t + 9 - w) % 10], acc[w]);
    }

    // store: fpart[b][s][(c*10+w)*2 + comp]
    float2* fp = (float2*)(fpart_g + ((size_t)b * 32 + s) * 320) + c * 10;
#pragma unroll
    for (int w = 0; w < 10; w++) fp[w] = u2f2(acc[w]);
}

// ---------------- kernel 2: amp + Linear(2C->2) + out filter + fused BN ----------------
// one block per b, 512 threads. Phase A: bulk-stage the 40KB fpart slice into
// smem with float4 loads (high MLP), reduce over s from smem. Last block to
// finish runs BatchNorm (reusing the staging smem).
__global__ void __launch_bounds__(512) stage23_kernel(const float* __restrict__ Wnl,
                                                      const float* __restrict__ WoR,
                                                      const float* __restrict__ WoI,
                                                      const float* __restrict__ gamma,
                                                      const float* __restrict__ beta,
                                                      float* __restrict__ out) {
    __shared__ __align__(16) float sbuf[10240];   // 40KB staging; reused as bnbuf
    __shared__ float tf[10][32];       // [w][i], i<16: amp*fr, i>=16: amp*fi
    __shared__ float contrib[10][32];  // [w][c*2+o]
    __shared__ int   lastflag;

    int b = blockIdx.x;
    int tid = threadIdx.x;

    // ---- phase A0: bulk stage fpart[b] (10240 floats) into smem, float4 ----
    {
        const float4* src4 = (const float4*)(fpart_g + (size_t)b * 10240);
        float4* dst4 = (float4*)sbuf;
#pragma unroll
        for (int i = 0; i < 5; i++) dst4[tid + i * 512] = src4[tid + i * 512];
    }
    __syncthreads();

    // ---- phase A1: reduce over s from smem; idx = (c*10+w)*2+o = tid ----
    if (tid < 320) {
        float v = 0.f;
#pragma unroll
        for (int s = 0; s < 32; s++) v += sbuf[s * 320 + tid];
        float other = __shfl_xor_sync(0xffffffffu, v, 1);
        float amp = v * v + other * other;
        int pair = tid >> 1;          // c*10 + w
        int o    = tid & 1;
        int c    = pair / 10;
        int w    = pair - c * 10;
        tf[w][c + 16 * o] = amp * v;  // o=0: amp*fr ; o=1: amp*fi
    }
    __syncthreads();

    // ---- phase B: Linear(2C->2) + output-filter weighting ----
    if (tid < 320) {
        int w = tid >> 5;
        int q = tid & 31;
        int c = q >> 1;
        int o = q & 1;
        float acc = 0.f;
        const float* wn = Wnl + (c * 2 + o) * 32;
#pragma unroll
        for (int i = 0; i < 32; i++) acc += tf[w][i] * wn[i];
        float wo = (o == 0 ? WoR : WoI)[c * 10 + w];
        contrib[w][q] = acc * wo;
    }
    __syncthreads();

    // ---- phase C: sum over w, write pre-BN output ----
    if (tid < 32) {
        float ssum = 0.f;
#pragma unroll
        for (int ww = 0; ww < 10; ww++) ssum += contrib[ww][tid];
        out_g[b * 32 + tid] = ssum;
    }
    __threadfence();
    __syncthreads();
    if (tid == 0) lastflag = (atomicAdd(&done_ctr, 1) == 255);
    __syncthreads();
    if (!lastflag) return;

    // ----- last block: BatchNorm over (b, o) per channel -----
    float (*bnbuf)[257] = (float (*)[257])sbuf;   // [q = ch*2+o][b], padded
    for (int i = tid; i < 8192; i += 512) {
        int bb = i >> 5;
        int q  = i & 31;
        bnbuf[q][bb] = __ldcg(&out_g[i]);
    }
    __syncthreads();

    // one warp per channel
    int ch = tid >> 5, lane = tid & 31;
    {
        float s1 = 0.f;
#pragma unroll
        for (int j = 0; j < 8; j++) {
            int bb = lane + j * 32;
            s1 += bnbuf[2 * ch][bb] + bnbuf[2 * ch + 1][bb];
        }
#pragma unroll
        for (int off = 16; off; off >>= 1) s1 += __shfl_xor_sync(0xffffffffu, s1, off);
        float mean = s1 * (1.f / 512.f);

        float s2 = 0.f;
#pragma unroll
        for (int j = 0; j < 8; j++) {
            int bb = lane + j * 32;
            float d0 = bnbuf[2 * ch][bb] - mean;
            float d1 = bnbuf[2 * ch + 1][bb] - mean;
            s2 += d0 * d0 + d1 * d1;
        }
#pragma unroll
        for (int off = 16; off; off >>= 1) s2 += __shfl_xor_sync(0xffffffffu, s2, off);
        float inv = rsqrtf(s2 * (1.f / 512.f) + 1e-5f);

        float g = gamma[ch], bb_ = beta[ch];
#pragma unroll
        for (int j = 0; j < 8; j++) {
            int bb = lane + j * 32;
            out[bb * 32 + 2 * ch]     = (bnbuf[2 * ch][bb] - mean) * inv * g + bb_;
            out[bb * 32 + 2 * ch + 1] = (bnbuf[2 * ch + 1][bb] - mean) * inv * g + bb_;
        }
    }

    // reset for next graph replay
    if (tid == 0) done_ctr = 0;
}

// ---------------- launch ----------------
extern "C" void kernel_launch(void* const* d_in, const int* in_sizes, int n_in,
                              void* d_out, int out_size) {
    const float* x     = (const float*)d_in[0];
    const float* wir   = (const float*)d_in[1];
    const float* wii   = (const float*)d_in[2];
    const float* wnl   = (const float*)d_in[3];
    const float* wor   = (const float*)d_in[4];
    const float* woi   = (const float*)d_in[5];
    const float* gamma = (const float*)d_in[6];
    const float* beta  = (const float*)d_in[7];
    float* out = (float*)d_out;

    stage1_kernel<<<dim3(16, 32), 256>>>(x, wir, wii);
    stage23_kernel<<<256, 512>>>(wnl, wor, woi, gamma, beta, out);
}